// round 1
// baseline (speedup 1.0000x reference)
#include <cuda_runtime.h>

#define BSZ      64
#define ENC_IN   64
#define ENC_HID  256
#define NNODES   2048
#define GHD      128
#define JTOT     (NNODES * GHD)      // 262144
#define LN_EPS   1e-5f

// ---------------- scratch (device globals: allocation-guard safe) ----------
__device__ float g_h1T[ENC_HID * BSZ];                 // [k][m] transposed h1
__device__ float g_buf0[(size_t)BSZ * NNODES * GHD];   // enc / layer input
__device__ float g_buf1[(size_t)BSZ * NNODES * GHD];   // layer-1 output

// ---------------- packed f32x2 helpers ------------------------------------
__device__ __forceinline__ unsigned long long d_fma2(unsigned long long a,
                                                     unsigned long long b,
                                                     unsigned long long c) {
    unsigned long long d;
    asm("fma.rn.f32x2 %0, %1, %2, %3;" : "=l"(d) : "l"(a), "l"(b), "l"(c));
    return d;
}
__device__ __forceinline__ void d_unpack(unsigned long long a, float& x, float& y) {
    asm("mov.b64 {%0, %1}, %2;" : "=f"(x), "=f"(y) : "l"(a));
}

// ===========================================================================
// K1: h1 = relu(x @ W1 + b1), stored transposed g_h1T[k][m]
// ===========================================================================
__global__ void k_enc1(const float* __restrict__ x,
                       const float* __restrict__ W1,
                       const float* __restrict__ b1) {
    const int b = blockIdx.x;
    const int j = threadIdx.x;
    __shared__ float sx[ENC_IN];
    if (j < ENC_IN) sx[j] = x[b * ENC_IN + j];
    __syncthreads();
    float acc = b1[j];
#pragma unroll
    for (int k = 0; k < ENC_IN; k++)
        acc = fmaf(sx[k], W1[k * ENC_HID + j], acc);
    g_h1T[j * BSZ + b] = fmaxf(acc, 0.0f);
}

// ===========================================================================
// K2: enc = h1 @ W2 + b2 -> g_buf0.  64x128 tile per block, f32x2 packed.
// ===========================================================================
__global__ __launch_bounds__(256) void k_enc2(const float* __restrict__ W2,
                                              const float* __restrict__ b2) {
    __shared__ __align__(16) float sWd[32 * 256];   // [k][2j] duplicated W2
    __shared__ __align__(16) float sH[32 * 64];     // [k][m] h1T panel

    const int tid = threadIdx.x;
    const int jg  = tid & 31;
    const int mg  = tid >> 5;
    const int j0  = blockIdx.x * 128;

    unsigned long long acc[4][4];
#pragma unroll
    for (int p = 0; p < 4; p++)
#pragma unroll
        for (int c = 0; c < 4; c++) acc[p][c] = 0ull;

    for (int pan = 0; pan < 8; pan++) {
        const int k0 = pan * 32;
        __syncthreads();
#pragma unroll
        for (int t = 0; t < 4; t++) {
            int i4 = tid + t * 256;
            int k  = i4 >> 5;
            int jj = i4 & 31;
            float4 w = *(const float4*)&W2[(size_t)(k0 + k) * JTOT + j0 + jj * 4];
            ((float4*)sWd)[k * 64 + jj * 2 + 0] = make_float4(w.x, w.x, w.y, w.y);
            ((float4*)sWd)[k * 64 + jj * 2 + 1] = make_float4(w.z, w.z, w.w, w.w);
        }
#pragma unroll
        for (int t = 0; t < 2; t++) {
            int i4 = tid + t * 256;
            int k  = i4 >> 4;
            int mm = i4 & 15;
            ((float4*)sH)[i4] = *(const float4*)&g_h1T[(k0 + k) * BSZ + mm * 4];
        }
        __syncthreads();

#pragma unroll
        for (int k = 0; k < 32; k++) {
            const unsigned long long* hp =
                (const unsigned long long*)&sH[k * 64 + mg * 8];
            unsigned long long h0 = hp[0], h1 = hp[1], h2 = hp[2], h3 = hp[3];
            const ulonglong2* wp = (const ulonglong2*)&sWd[k * 256 + jg * 8];
            ulonglong2 wa = wp[0];
            ulonglong2 wb = wp[1];
            acc[0][0] = d_fma2(h0, wa.x, acc[0][0]);
            acc[1][0] = d_fma2(h1, wa.x, acc[1][0]);
            acc[2][0] = d_fma2(h2, wa.x, acc[2][0]);
            acc[3][0] = d_fma2(h3, wa.x, acc[3][0]);
            acc[0][1] = d_fma2(h0, wa.y, acc[0][1]);
            acc[1][1] = d_fma2(h1, wa.y, acc[1][1]);
            acc[2][1] = d_fma2(h2, wa.y, acc[2][1]);
            acc[3][1] = d_fma2(h3, wa.y, acc[3][1]);
            acc[0][2] = d_fma2(h0, wb.x, acc[0][2]);
            acc[1][2] = d_fma2(h1, wb.x, acc[1][2]);
            acc[2][2] = d_fma2(h2, wb.x, acc[2][2]);
            acc[3][2] = d_fma2(h3, wb.x, acc[3][2]);
            acc[0][3] = d_fma2(h0, wb.y, acc[0][3]);
            acc[1][3] = d_fma2(h1, wb.y, acc[1][3]);
            acc[2][3] = d_fma2(h2, wb.y, acc[2][3]);
            acc[3][3] = d_fma2(h3, wb.y, acc[3][3]);
        }
    }

    float4 b2v = *(const float4*)&b2[j0 + jg * 4];
#pragma unroll
    for (int p = 0; p < 4; p++) {
        float lo[4], hi[4];
#pragma unroll
        for (int c = 0; c < 4; c++) d_unpack(acc[p][c], lo[c], hi[c]);
        int m = mg * 8 + 2 * p;
        *(float4*)&g_buf0[(size_t)m * JTOT + j0 + jg * 4] =
            make_float4(lo[0] + b2v.x, lo[1] + b2v.y, lo[2] + b2v.z, lo[3] + b2v.w);
        *(float4*)&g_buf0[(size_t)(m + 1) * JTOT + j0 + jg * 4] =
            make_float4(hi[0] + b2v.x, hi[1] + b2v.y, hi[2] + b2v.z, hi[3] + b2v.w);
    }
}

// ===========================================================================
// K3/K4: fused GCN layer (LN + 128x128 GEMM + chain aggregation + residual;
// layer 2 fuses the final Wout projection).  grid(69,64) block(128).
// ===========================================================================
__global__ __launch_bounds__(128) void k_gcn(const float* __restrict__ Ah,
                                             const float* __restrict__ Wg,
                                             const float* __restrict__ gam,
                                             const float* __restrict__ bet,
                                             const float* __restrict__ Wout,
                                             const float* __restrict__ bout,
                                             float* __restrict__ proj,
                                             int dir) {
    __shared__ __align__(16) float sX[32 * 128];    // input rows, reused as Wx
    __shared__ __align__(16) float sHT[128 * 34];   // LN output transposed
    __shared__ __align__(16) float sWgd[8 * 256];   // duplicated Wg panel
    __shared__ float sAp[32], sAn[32];
    __shared__ float sGam[128], sBet[128], sWo[128];

    const float* in  = dir ? g_buf1 : g_buf0;
    float*       out = g_buf1;

    const int tid  = threadIdx.x;
    const int lane = tid & 31;
    const int w    = tid >> 5;
    const int b    = blockIdx.y;
    const int n0   = blockIdx.x * 30;

    for (int i4 = tid; i4 < 1024; i4 += 128) {
        int r  = i4 >> 5;
        int c4 = i4 & 31;
        int gi = n0 - 1 + r;
        gi = max(0, min(NNODES - 1, gi));
        ((float4*)sX)[i4] =
            *(const float4*)&in[((size_t)b * NNODES + gi) * GHD + c4 * 4];
    }
    if (tid < 128) {
        sGam[tid] = gam[tid];
        sBet[tid] = bet[tid];
        sWo[tid]  = dir ? Wout[tid] : 0.0f;
    }
    if (tid < 32) {
        int gi = n0 - 1 + tid;
        sAp[tid] = (gi >= 1 && gi < NNODES) ? Ah[(size_t)gi * NNODES + gi - 1] : 0.0f;
        sAn[tid] = (gi >= 0 && gi < NNODES - 1) ? Ah[(size_t)gi * NNODES + gi + 1] : 0.0f;
    }
    __syncthreads();

#pragma unroll
    for (int rr = 0; rr < 8; rr++) {
        int r = w * 8 + rr;
        float4 v = ((float4*)sX)[r * 32 + lane];
        float s = v.x + v.y + v.z + v.w;
        float q = v.x * v.x + v.y * v.y + v.z * v.z + v.w * v.w;
#pragma unroll
        for (int o = 16; o; o >>= 1) {
            s += __shfl_xor_sync(0xFFFFFFFFu, s, o);
            q += __shfl_xor_sync(0xFFFFFFFFu, q, o);
        }
        float mu   = s * (1.0f / GHD);
        float rstd = rsqrtf(fmaxf(q * (1.0f / GHD) - mu * mu, 0.0f) + LN_EPS);
        int c = lane * 4;
        sHT[(c + 0) * 34 + r] = (v.x - mu) * rstd * sGam[c + 0] + sBet[c + 0];
        sHT[(c + 1) * 34 + r] = (v.y - mu) * rstd * sGam[c + 1] + sBet[c + 1];
        sHT[(c + 2) * 34 + r] = (v.z - mu) * rstd * sGam[c + 2] + sBet[c + 2];
        sHT[(c + 3) * 34 + r] = (v.w - mu) * rstd * sGam[c + 3] + sBet[c + 3];
    }
    __syncthreads();

    const int jg = lane;
    const int mg = w;
    unsigned long long acc[4][4];
#pragma unroll
    for (int p = 0; p < 4; p++)
#pragma unroll
        for (int c = 0; c < 4; c++) acc[p][c] = 0ull;

    for (int pan = 0; pan < 16; pan++) {
        const int k0 = pan * 8;
        if (pan) __syncthreads();
#pragma unroll
        for (int t = 0; t < 2; t++) {
            int i4 = tid + t * 128;
            int k  = i4 >> 5;
            int jj = i4 & 31;
            float4 wv = *(const float4*)&Wg[(k0 + k) * GHD + jj * 4];
            ((float4*)sWgd)[k * 64 + jj * 2 + 0] = make_float4(wv.x, wv.x, wv.y, wv.y);
            ((float4*)sWgd)[k * 64 + jj * 2 + 1] = make_float4(wv.z, wv.z, wv.w, wv.w);
        }
        __syncthreads();

#pragma unroll
        for (int k = 0; k < 8; k++) {
            const unsigned long long* hp =
                (const unsigned long long*)&sHT[(k0 + k) * 34 + mg * 8];
            unsigned long long h0 = hp[0], h1 = hp[1], h2 = hp[2], h3 = hp[3];
            const ulonglong2* wp = (const ulonglong2*)&sWgd[k * 256 + jg * 8];
            ulonglong2 wa = wp[0];
            ulonglong2 wb = wp[1];
            acc[0][0] = d_fma2(h0, wa.x, acc[0][0]);
            acc[1][0] = d_fma2(h1, wa.x, acc[1][0]);
            acc[2][0] = d_fma2(h2, wa.x, acc[2][0]);
            acc[3][0] = d_fma2(h3, wa.x, acc[3][0]);
            acc[0][1] = d_fma2(h0, wa.y, acc[0][1]);
            acc[1][1] = d_fma2(h1, wa.y, acc[1][1]);
            acc[2][1] = d_fma2(h2, wa.y, acc[2][1]);
            acc[3][1] = d_fma2(h3, wa.y, acc[3][1]);
            acc[0][2] = d_fma2(h0, wb.x, acc[0][2]);
            acc[1][2] = d_fma2(h1, wb.x, acc[1][2]);
            acc[2][2] = d_fma2(h2, wb.x, acc[2][2]);
            acc[3][2] = d_fma2(h3, wb.x, acc[3][2]);
            acc[0][3] = d_fma2(h0, wb.y, acc[0][3]);
            acc[1][3] = d_fma2(h1, wb.y, acc[1][3]);
            acc[2][3] = d_fma2(h2, wb.y, acc[2][3]);
            acc[3][3] = d_fma2(h3, wb.y, acc[3][3]);
        }
    }

    float* sWx = sX;
#pragma unroll
    for (int p = 0; p < 4; p++) {
        float lo[4], hi[4];
#pragma unroll
        for (int c = 0; c < 4; c++) d_unpack(acc[p][c], lo[c], hi[c]);
        int m = mg * 8 + 2 * p;
        ((float4*)sWx)[m * 32 + jg]       = make_float4(lo[0], lo[1], lo[2], lo[3]);
        ((float4*)sWx)[(m + 1) * 32 + jg] = make_float4(hi[0], hi[1], hi[2], hi[3]);
    }
    __syncthreads();

    for (int r = 1 + w; r <= 30; r += 4) {
        int gi = n0 + r - 1;
        if (gi >= NNODES) break;
        int c = lane * 4;
        float4 iv = *(const float4*)&in[((size_t)b * NNODES + gi) * GHD + c];
        float4 wp = ((float4*)sWx)[(r - 1) * 32 + lane];
        float4 wn = ((float4*)sWx)[(r + 1) * 32 + lane];
        float ap = sAp[r], an = sAn[r];
        float4 o;
        o.x = fmaf(an, wn.x, fmaf(ap, wp.x, iv.x));
        o.y = fmaf(an, wn.y, fmaf(ap, wp.y, iv.y));
        o.z = fmaf(an, wn.z, fmaf(ap, wp.z, iv.z));
        o.w = fmaf(an, wn.w, fmaf(ap, wp.w, iv.w));
        if (!dir) {
            *(float4*)&out[((size_t)b * NNODES + gi) * GHD + c] = o;
        } else {
            float s = o.x * sWo[c] + o.y * sWo[c + 1] + o.z * sWo[c + 2] + o.w * sWo[c + 3];
#pragma unroll
            for (int off = 16; off; off >>= 1)
                s += __shfl_xor_sync(0xFFFFFFFFu, s, off);
            if (lane == 0) proj[b * NNODES + gi] = s + bout[0];
        }
    }
}

// ===========================================================================
extern "C" void kernel_launch(void* const* d_in, const int* in_sizes, int n_in,
                              void* d_out, int out_size) {
    const float* x    = (const float*)d_in[0];
    const float* Ah   = (const float*)d_in[1];
    const float* W1   = (const float*)d_in[2];
    const float* b1   = (const float*)d_in[3];
    const float* W2   = (const float*)d_in[4];
    const float* b2   = (const float*)d_in[5];
    const float* Wg1  = (const float*)d_in[6];
    const float* Wg2  = (const float*)d_in[7];
    const float* g1   = (const float*)d_in[8];
    const float* bb1  = (const float*)d_in[9];
    const float* g2   = (const float*)d_in[10];
    const float* bb2  = (const float*)d_in[11];
    const float* Wout = (const float*)d_in[12];
    const float* bout = (const float*)d_in[13];
    float* out = (float*)d_out;

    k_enc1<<<BSZ, ENC_HID>>>(x, W1, b1);
    k_enc2<<<JTOT / 128, 256>>>(W2, b2);
    dim3 gcn_grid(69, BSZ);
    k_gcn<<<gcn_grid, 128>>>(Ah, Wg1, g1, bb1, Wout, bout, out, 0);
    k_gcn<<<gcn_grid, 128>>>(Ah, Wg2, g2, bb2, Wout, bout, out, 1);
}

// round 3
// speedup vs baseline: 1.7409x; 1.7409x over previous
#include <cuda_runtime.h>
#include <cuda_bf16.h>

typedef unsigned int       u32;
typedef unsigned long long u64;

#define BSZ      64
#define ENC_IN   64
#define ENC_HID  256
#define NNODES   2048
#define GHD      128
#define JTOT     (NNODES * GHD)      // 262144
#define LN_EPS   1e-5f

// ---------------- scratch (device globals: allocation-guard safe) ----------
__device__ float g_h1[BSZ * ENC_HID];                  // [m][k] h1 rows
__device__ float g_buf0[(size_t)BSZ * NNODES * GHD];   // enc / layer input
__device__ float g_buf1[(size_t)BSZ * NNODES * GHD];   // layer-1 output
// Wg transposed [n][k] bf16 hi/lo images, row stride 136 halfs (= 68 u32)
__device__ __align__(16) u32 g_BH[2][GHD * 68];
__device__ __align__(16) u32 g_BL[2][GHD * 68];

extern __shared__ __align__(1024) char dynsm[];

// ---------------- helpers ---------------------------------------------------
__device__ __forceinline__ u32 smem_u32(const void* p) {
    u32 a;
    asm("{ .reg .u64 t; cvta.to.shared.u64 t, %1; cvt.u32.u64 %0, t; }"
        : "=r"(a) : "l"(p));
    return a;
}
__device__ __forceinline__ void ldsm4(u32* r, u32 a) {
    asm volatile("ldmatrix.sync.aligned.m8n8.x4.shared.b16 {%0,%1,%2,%3}, [%4];"
                 : "=r"(r[0]), "=r"(r[1]), "=r"(r[2]), "=r"(r[3]) : "r"(a));
}
__device__ __forceinline__ void ldsm4t(u32* r, u32 a) {
    asm volatile("ldmatrix.sync.aligned.m8n8.x4.trans.shared.b16 {%0,%1,%2,%3}, [%4];"
                 : "=r"(r[0]), "=r"(r[1]), "=r"(r[2]), "=r"(r[3]) : "r"(a));
}
__device__ __forceinline__ void mma16816(float* c, const u32* a, u32 b0, u32 b1) {
    asm volatile(
        "mma.sync.aligned.m16n8k16.row.col.f32.bf16.bf16.f32 "
        "{%0,%1,%2,%3}, {%4,%5,%6,%7}, {%8,%9}, {%0,%1,%2,%3};"
        : "+f"(c[0]), "+f"(c[1]), "+f"(c[2]), "+f"(c[3])
        : "r"(a[0]), "r"(a[1]), "r"(a[2]), "r"(a[3]), "r"(b0), "r"(b1));
}
__device__ __forceinline__ void split2(float a, float b, u32& hi, u32& lo) {
    __nv_bfloat162 h = __floats2bfloat162_rn(a, b);
    float ha = __bfloat162float(h.x), hb = __bfloat162float(h.y);
    __nv_bfloat162 l = __floats2bfloat162_rn(a - ha, b - hb);
    hi = *reinterpret_cast<u32*>(&h);
    lo = *reinterpret_cast<u32*>(&l);
}

// ===========================================================================
// K0: Wg -> transposed [n][k] bf16 hi/lo images (stride 136 halfs)
// ===========================================================================
__global__ void k_prep(const float* __restrict__ Wg1, const float* __restrict__ Wg2) {
    const int L = blockIdx.x;
    const float* Wg = L ? Wg2 : Wg1;
    const int n = threadIdx.x;   // 0..127
    for (int k = 0; k < GHD; k += 2) {
        u32 hi, lo;
        split2(Wg[k * GHD + n], Wg[(k + 1) * GHD + n], hi, lo);
        g_BH[L][n * 68 + (k >> 1)] = hi;
        g_BL[L][n * 68 + (k >> 1)] = lo;
    }
}

// ===========================================================================
// K1: h1 = relu(x @ W1 + b1), row-major [m][k]
// ===========================================================================
__global__ void k_enc1(const float* __restrict__ x,
                       const float* __restrict__ W1,
                       const float* __restrict__ b1) {
    const int b = blockIdx.x;
    const int j = threadIdx.x;
    __shared__ float sx[ENC_IN];
    if (j < ENC_IN) sx[j] = x[b * ENC_IN + j];
    __syncthreads();
    float acc = b1[j];
#pragma unroll
    for (int k = 0; k < ENC_IN; k++)
        acc = fmaf(sx[k], W1[k * ENC_HID + j], acc);
    g_h1[b * ENC_HID + j] = fmaxf(acc, 0.0f);
}

// ===========================================================================
// K2: enc = h1 @ W2 + b2 -> g_buf0.  mma.sync bf16-split, M=64 N=256 K=256.
// grid(1024) block(256). smem: A hi/lo (full K) + B hi/lo (64-row panels).
// ===========================================================================
#define ESB      528                       // bytes per smem row (264 halfs)
#define E_OFF_AHI 0
#define E_OFF_ALO 33792
#define E_OFF_BHI 67584
#define E_OFF_BLO 101376
#define E_SMEM    135168

__global__ __launch_bounds__(256) void k_enc2_mma(const float* __restrict__ W2,
                                                  const float* __restrict__ b2) {
    const int tid = threadIdx.x;
    const int L   = tid & 31;
    const int w   = tid >> 5;
    const int j0  = blockIdx.x * 256;
    const u32 sb  = smem_u32(dynsm);

    // ---- stage A = h1 (bf16 hi/lo), full K ----
    for (int i = tid; i < 4096; i += 256) {
        int row = i >> 6, c4 = i & 63;
        float4 v = *(const float4*)&g_h1[row * ENC_HID + c4 * 4];
        u32 h0, l0, h1, l1;
        split2(v.x, v.y, h0, l0);
        split2(v.z, v.w, h1, l1);
        *(uint2*)(dynsm + E_OFF_AHI + row * ESB + c4 * 8) = make_uint2(h0, h1);
        *(uint2*)(dynsm + E_OFF_ALO + row * ESB + c4 * 8) = make_uint2(l0, l1);
    }

    const int mw = w & 1, nw = w >> 1;
    const int R0 = mw * 32, N0 = nw * 64;
    const u32 arow = (u32)(L & 15);
    const u32 kcol = (u32)((L >> 4) << 3);
    const u32 brow = (u32)((L & 7) + ((L >> 3) & 1) * 8);
    const u32 bcol = (u32)((L >> 4) << 3);

    float acc[2][8][4];
#pragma unroll
    for (int mt = 0; mt < 2; mt++)
#pragma unroll
        for (int j = 0; j < 8; j++)
#pragma unroll
            for (int c = 0; c < 4; c++) acc[mt][j][c] = 0.0f;

    for (int kp = 0; kp < 4; kp++) {
        __syncthreads();
        // stage B panel = W2[kp*64 .. +63][j0 .. j0+255] (bf16 hi/lo)
        for (int i = tid; i < 4096; i += 256) {
            int row = i >> 6, c4 = i & 63;
            float4 v = *(const float4*)&W2[(size_t)(kp * 64 + row) * JTOT + j0 + c4 * 4];
            u32 h0, l0, h1, l1;
            split2(v.x, v.y, h0, l0);
            split2(v.z, v.w, h1, l1);
            *(uint2*)(dynsm + E_OFF_BHI + row * ESB + c4 * 8) = make_uint2(h0, h1);
            *(uint2*)(dynsm + E_OFF_BLO + row * ESB + c4 * 8) = make_uint2(l0, l1);
        }
        __syncthreads();

#pragma unroll
        for (int p = 0; p < 3; p++) {
            const u32 aOff = (p < 2) ? E_OFF_AHI : E_OFF_ALO;
            const u32 bOff = (p == 1) ? E_OFF_BLO : E_OFF_BHI;
#pragma unroll
            for (int ks = 0; ks < 4; ks++) {
                u32 a0[4], a1[4];
                u32 ka = (u32)((kp * 64 + ks * 16 + kcol) * 2);
                ldsm4(a0, sb + aOff + (R0 + arow) * ESB + ka);
                ldsm4(a1, sb + aOff + (R0 + 16 + arow) * ESB + ka);
                u32 bf[4][4];
                u32 kb = (u32)((ks * 16 + brow) * ESB);
#pragma unroll
                for (int nt = 0; nt < 4; nt++)
                    ldsm4t(bf[nt], sb + bOff + kb + (N0 + nt * 16 + bcol) * 2);
#pragma unroll
                for (int j = 0; j < 8; j++) {
                    u32 b0 = bf[j >> 1][(j & 1) * 2];
                    u32 b1 = bf[j >> 1][(j & 1) * 2 + 1];
                    mma16816(acc[0][j], a0, b0, b1);
                    mma16816(acc[1][j], a1, b0, b1);
                }
            }
        }
    }

    // ---- epilogue: + b2, store ----
#pragma unroll
    for (int mt = 0; mt < 2; mt++) {
        int m = R0 + mt * 16 + (L >> 2);
#pragma unroll
        for (int j = 0; j < 8; j++) {
            int n = j0 + N0 + j * 8 + (L & 3) * 2;
            float b20 = __ldg(&b2[n]), b21 = __ldg(&b2[n + 1]);
            *(float2*)&g_buf0[(size_t)m * JTOT + n] =
                make_float2(acc[mt][j][0] + b20, acc[mt][j][1] + b21);
            *(float2*)&g_buf0[(size_t)(m + 8) * JTOT + n] =
                make_float2(acc[mt][j][2] + b20, acc[mt][j][3] + b21);
        }
    }
}

// ===========================================================================
// K3/K4: fused GCN layer, mma.sync bf16-split.  M=128 rows (126 out + halo),
// N=K=128.  grid(17,64) block(256).
// ===========================================================================
#define GSB       272                      // bytes per smem row (136 halfs)
#define G_OFF_AHI 0
#define G_OFF_ALO 34816
#define G_OFF_BHI 69632
#define G_OFF_BLO 104448
#define G_SMEM    139264

__global__ __launch_bounds__(256) void k_gcn_mma(const float* __restrict__ Ah,
                                                 const float* __restrict__ gam,
                                                 const float* __restrict__ bet,
                                                 const float* __restrict__ Wout,
                                                 const float* __restrict__ bout,
                                                 float* __restrict__ proj,
                                                 int layer) {
    __shared__ float sAp[128], sAn[128], sGam[128], sBet[128], sWo[128];

    const float* in  = layer ? g_buf1 : g_buf0;
    float*       out = g_buf1;

    const int tid = threadIdx.x;
    const int L   = tid & 31;
    const int w   = tid >> 5;
    const int b   = blockIdx.y;
    const int n0  = blockIdx.x * 126;
    const u32 sb  = smem_u32(dynsm);

    // ---- stage B (hi/lo) via linear copy ----
    {
        uint4* dh = (uint4*)(dynsm + G_OFF_BHI);
        uint4* dl = (uint4*)(dynsm + G_OFF_BLO);
        const uint4* shp = (const uint4*)g_BH[layer];
        const uint4* slp = (const uint4*)g_BL[layer];
        for (int i = tid; i < 2176; i += 256) {
            dh[i] = shp[i];
            dl[i] = slp[i];
        }
    }
    if (tid < 128) {
        sGam[tid] = gam[tid];
        sBet[tid] = bet[tid];
        sWo[tid]  = layer ? Wout[tid] : 0.0f;
        int gi = n0 - 1 + tid;
        sAp[tid] = (gi >= 1 && gi < NNODES) ? Ah[(size_t)gi * NNODES + gi - 1] : 0.0f;
        sAn[tid] = (gi >= 0 && gi < NNODES - 1) ? Ah[(size_t)gi * NNODES + gi + 1] : 0.0f;
    }
    __syncthreads();

    // ---- LN + bf16 split -> A tiles (warp w: rows 16w..16w+15) ----
#pragma unroll 2
    for (int rr = 0; rr < 16; rr++) {
        int r  = w * 16 + rr;
        int gi = min(NNODES - 1, max(0, n0 - 1 + r));
        float4 v = *(const float4*)&in[((size_t)b * NNODES + gi) * GHD + L * 4];
        float s = v.x + v.y + v.z + v.w;
        float q = v.x * v.x + v.y * v.y + v.z * v.z + v.w * v.w;
#pragma unroll
        for (int o = 16; o; o >>= 1) {
            s += __shfl_xor_sync(0xFFFFFFFFu, s, o);
            q += __shfl_xor_sync(0xFFFFFFFFu, q, o);
        }
        float mu   = s * (1.0f / GHD);
        float rstd = rsqrtf(fmaxf(q * (1.0f / GHD) - mu * mu, 0.0f) + LN_EPS);
        int c = L * 4;
        float f0 = (v.x - mu) * rstd * sGam[c + 0] + sBet[c + 0];
        float f1 = (v.y - mu) * rstd * sGam[c + 1] + sBet[c + 1];
        float f2 = (v.z - mu) * rstd * sGam[c + 2] + sBet[c + 2];
        float f3 = (v.w - mu) * rstd * sGam[c + 3] + sBet[c + 3];
        u32 h0, l0, h1, l1;
        split2(f0, f1, h0, l0);
        split2(f2, f3, h1, l1);
        *(uint2*)(dynsm + G_OFF_AHI + r * GSB + L * 8) = make_uint2(h0, h1);
        *(uint2*)(dynsm + G_OFF_ALO + r * GSB + L * 8) = make_uint2(l0, l1);
    }
    __syncthreads();

    // ---- MMA: warp (mw,nw) computes 32M x 64N ----
    const int mw = w & 3, nw = w >> 2;
    const int R0 = mw * 32, N0 = nw * 64;
    const u32 arow = (u32)(L & 15);
    const u32 kcol = (u32)((L >> 4) << 3);

    float acc[2][8][4];
#pragma unroll
    for (int mt = 0; mt < 2; mt++)
#pragma unroll
        for (int j = 0; j < 8; j++)
#pragma unroll
            for (int c = 0; c < 4; c++) acc[mt][j][c] = 0.0f;

#pragma unroll
    for (int p = 0; p < 3; p++) {
        const u32 aOff = (p < 2) ? G_OFF_AHI : G_OFF_ALO;
        const u32 bOff = (p == 1) ? G_OFF_BLO : G_OFF_BHI;
#pragma unroll
        for (int ks = 0; ks < 8; ks++) {
            u32 kb = (u32)((ks * 16 + kcol) * 2);
            u32 a0[4], a1[4];
            ldsm4(a0, sb + aOff + (R0 + arow) * GSB + kb);
            ldsm4(a1, sb + aOff + (R0 + 16 + arow) * GSB + kb);
            u32 bf[4][4];
#pragma unroll
            for (int nt = 0; nt < 4; nt++)
                ldsm4(bf[nt], sb + bOff + (N0 + nt * 16 + arow) * GSB + kb);
#pragma unroll
            for (int j = 0; j < 8; j++) {
                u32 b0 = bf[j >> 1][(j & 1)];
                u32 b1 = bf[j >> 1][(j & 1) + 2];
                mma16816(acc[0][j], a0, b0, b1);
                mma16816(acc[1][j], a1, b0, b1);
            }
        }
    }
    __syncthreads();

    // ---- C frags -> sC (stride 132 floats; reuses A region) ----
    float* sC = (float*)dynsm;
#pragma unroll
    for (int mt = 0; mt < 2; mt++) {
        int m = R0 + mt * 16 + (L >> 2);
#pragma unroll
        for (int j = 0; j < 8; j++) {
            int n = N0 + j * 8 + (L & 3) * 2;
            *(float2*)&sC[m * 132 + n]       = make_float2(acc[mt][j][0], acc[mt][j][1]);
            *(float2*)&sC[(m + 8) * 132 + n] = make_float2(acc[mt][j][2], acc[mt][j][3]);
        }
    }
    __syncthreads();

    // ---- aggregate: out = in + ap*Wx[r-1] + an*Wx[r+1]; layer2 projects ----
    for (int r = 1 + w; r <= 126; r += 8) {
        int gi = n0 + r - 1;
        if (gi >= NNODES) continue;
        int c = L * 4;
        float4 iv = *(const float4*)&in[((size_t)b * NNODES + gi) * GHD + c];
        float4 wp = *(const float4*)&sC[(r - 1) * 132 + c];
        float4 wn = *(const float4*)&sC[(r + 1) * 132 + c];
        float ap = sAp[r], an = sAn[r];
        float4 o;
        o.x = fmaf(an, wn.x, fmaf(ap, wp.x, iv.x));
        o.y = fmaf(an, wn.y, fmaf(ap, wp.y, iv.y));
        o.z = fmaf(an, wn.z, fmaf(ap, wp.z, iv.z));
        o.w = fmaf(an, wn.w, fmaf(ap, wp.w, iv.w));
        if (!layer) {
            *(float4*)&out[((size_t)b * NNODES + gi) * GHD + c] = o;
        } else {
            float s = o.x * sWo[c] + o.y * sWo[c + 1] + o.z * sWo[c + 2] + o.w * sWo[c + 3];
#pragma unroll
            for (int off = 16; off; off >>= 1)
                s += __shfl_xor_sync(0xFFFFFFFFu, s, off);
            if (L == 0) proj[b * NNODES + gi] = s + bout[0];
        }
    }
}

// ===========================================================================
extern "C" void kernel_launch(void* const* d_in, const int* in_sizes, int n_in,
                              void* d_out, int out_size) {
    const float* x    = (const float*)d_in[0];
    const float* Ah   = (const float*)d_in[1];
    const float* W1   = (const float*)d_in[2];
    const float* b1   = (const float*)d_in[3];
    const float* W2   = (const float*)d_in[4];
    const float* b2   = (const float*)d_in[5];
    const float* Wg1  = (const float*)d_in[6];
    const float* Wg2  = (const float*)d_in[7];
    const float* g1   = (const float*)d_in[8];
    const float* bb1  = (const float*)d_in[9];
    const float* g2   = (const float*)d_in[10];
    const float* bb2  = (const float*)d_in[11];
    const float* Wout = (const float*)d_in[12];
    const float* bout = (const float*)d_in[13];
    float* out = (float*)d_out;

    cudaFuncSetAttribute(k_enc2_mma, cudaFuncAttributeMaxDynamicSharedMemorySize,
                         E_SMEM);
    cudaFuncSetAttribute(k_gcn_mma, cudaFuncAttributeMaxDynamicSharedMemorySize,
                         G_SMEM);

    k_prep<<<2, GHD>>>(Wg1, Wg2);
    k_enc1<<<BSZ, ENC_HID>>>(x, W1, b1);
    k_enc2_mma<<<JTOT / 256, 256, E_SMEM>>>(W2, b2);
    dim3 gcn_grid(17, BSZ);
    k_gcn_mma<<<gcn_grid, 256, G_SMEM>>>(Ah, g1, bb1, Wout, bout, out, 0);
    k_gcn_mma<<<gcn_grid, 256, G_SMEM>>>(Ah, g2, bb2, Wout, bout, out, 1);
}

// round 4
// speedup vs baseline: 2.4144x; 1.3869x over previous
#include <cuda_runtime.h>
#include <cuda_bf16.h>

typedef unsigned int       u32;
typedef unsigned long long u64;

#define BSZ      64
#define ENC_IN   64
#define ENC_HID  256
#define NNODES   2048
#define GHD      128
#define JTOT     (NNODES * GHD)      // 262144
#define LN_EPS   1e-5f

// ---------------- scratch (device globals: allocation-guard safe) ----------
__device__ float g_h1[BSZ * ENC_HID];                  // [m][k] h1 rows
__device__ float g_buf0[(size_t)BSZ * NNODES * GHD];   // enc / layer input
__device__ float g_buf1[(size_t)BSZ * NNODES * GHD];   // layer-1 output
// Wg transposed [n][k] bf16 hi/lo images, row stride 136 halfs (= 68 u32)
__device__ __align__(16) u32 g_BH[2][GHD * 68];
__device__ __align__(16) u32 g_BL[2][GHD * 68];

extern __shared__ __align__(1024) char dynsm[];

// ---------------- helpers ---------------------------------------------------
__device__ __forceinline__ u32 smem_u32(const void* p) {
    u32 a;
    asm("{ .reg .u64 t; cvta.to.shared.u64 t, %1; cvt.u32.u64 %0, t; }"
        : "=r"(a) : "l"(p));
    return a;
}
__device__ __forceinline__ void ldsm4(u32* r, u32 a) {
    asm volatile("ldmatrix.sync.aligned.m8n8.x4.shared.b16 {%0,%1,%2,%3}, [%4];"
                 : "=r"(r[0]), "=r"(r[1]), "=r"(r[2]), "=r"(r[3]) : "r"(a));
}
__device__ __forceinline__ void ldsm4t(u32* r, u32 a) {
    asm volatile("ldmatrix.sync.aligned.m8n8.x4.trans.shared.b16 {%0,%1,%2,%3}, [%4];"
                 : "=r"(r[0]), "=r"(r[1]), "=r"(r[2]), "=r"(r[3]) : "r"(a));
}
__device__ __forceinline__ void mma16816(float* c, const u32* a, u32 b0, u32 b1) {
    asm volatile(
        "mma.sync.aligned.m16n8k16.row.col.f32.bf16.bf16.f32 "
        "{%0,%1,%2,%3}, {%4,%5,%6,%7}, {%8,%9}, {%0,%1,%2,%3};"
        : "+f"(c[0]), "+f"(c[1]), "+f"(c[2]), "+f"(c[3])
        : "r"(a[0]), "r"(a[1]), "r"(a[2]), "r"(a[3]), "r"(b0), "r"(b1));
}
__device__ __forceinline__ void split2(float a, float b, u32& hi, u32& lo) {
    __nv_bfloat162 h = __floats2bfloat162_rn(a, b);
    float ha = __bfloat162float(h.x), hb = __bfloat162float(h.y);
    __nv_bfloat162 l = __floats2bfloat162_rn(a - ha, b - hb);
    hi = *reinterpret_cast<u32*>(&h);
    lo = *reinterpret_cast<u32*>(&l);
}

// ===========================================================================
// K0: Wg -> transposed [n][k] bf16 hi/lo images (stride 136 halfs)
// ===========================================================================
__global__ void k_prep(const float* __restrict__ Wg1, const float* __restrict__ Wg2) {
    const int L = blockIdx.x;
    const float* Wg = L ? Wg2 : Wg1;
    const int n = threadIdx.x;   // 0..127
    for (int k = 0; k < GHD; k += 2) {
        u32 hi, lo;
        split2(Wg[k * GHD + n], Wg[(k + 1) * GHD + n], hi, lo);
        g_BH[L][n * 68 + (k >> 1)] = hi;
        g_BL[L][n * 68 + (k >> 1)] = lo;
    }
}

// ===========================================================================
// K1: h1 = relu(x @ W1 + b1), row-major [m][k]
// ===========================================================================
__global__ void k_enc1(const float* __restrict__ x,
                       const float* __restrict__ W1,
                       const float* __restrict__ b1) {
    const int b = blockIdx.x;
    const int j = threadIdx.x;
    __shared__ float sx[ENC_IN];
    if (j < ENC_IN) sx[j] = x[b * ENC_IN + j];
    __syncthreads();
    float acc = b1[j];
#pragma unroll
    for (int k = 0; k < ENC_IN; k++)
        acc = fmaf(sx[k], W1[k * ENC_HID + j], acc);
    g_h1[b * ENC_HID + j] = fmaxf(acc, 0.0f);
}

// ===========================================================================
// K2: enc = h1 @ W2 + b2 -> g_buf0.  M=64 N=128, K=256 in 8 k32 panels.
// 2 blocks/SM (85KB smem, <=128 regs), register prefetch of next panel.
// ===========================================================================
#define ESB       528                      // A row stride bytes (264 halfs)
#define EBB       272                      // B row stride bytes (136 halfs)
#define E_AHI     0
#define E_ALO     33792
#define E_BHI     67584
#define E_BLO     76288
#define E_SMEM    84992

__global__ __launch_bounds__(256, 2) void k_enc2_mma(const float* __restrict__ W2,
                                                     const float* __restrict__ b2) {
    const int tid = threadIdx.x;
    const int L   = tid & 31;
    const int w   = tid >> 5;
    const int j0  = blockIdx.x * 128;
    const u32 sb  = smem_u32(dynsm);

    // ---- stage A = h1 (bf16 hi/lo), full K=256 ----
    for (int i = tid; i < 4096; i += 256) {
        int row = i >> 6, c4 = i & 63;
        float4 v = *(const float4*)&g_h1[row * ENC_HID + c4 * 4];
        u32 h0, l0, h1, l1;
        split2(v.x, v.y, h0, l0);
        split2(v.z, v.w, h1, l1);
        *(uint2*)(dynsm + E_AHI + row * ESB + c4 * 8) = make_uint2(h0, h1);
        *(uint2*)(dynsm + E_ALO + row * ESB + c4 * 8) = make_uint2(l0, l1);
    }

    const int mw = w & 1, nw = w >> 1;
    const int R0 = mw * 32, N0 = nw * 32;
    const u32 arow = (u32)(L & 15);
    const u32 kcol = (u32)((L >> 4) << 3);
    const u32 brow = (u32)((L & 7) + ((L >> 3) & 1) * 8);
    const u32 bcol = (u32)((L >> 4) << 3);

    float acc[2][4][4];
#pragma unroll
    for (int mt = 0; mt < 2; mt++)
#pragma unroll
        for (int j = 0; j < 4; j++)
#pragma unroll
            for (int c = 0; c < 4; c++) acc[mt][j][c] = 0.0f;

    // prefetch panel 0 (4 float4/thread: 32x128 floats)
    const int prow = tid >> 3, pc4 = ((tid & 7) << 2);
    float4 pf[4];
#pragma unroll
    for (int t = 0; t < 4; t++)
        pf[t] = *(const float4*)&W2[(size_t)(prow + t * 32 % 32 + 0) * JTOT +
                                    j0 + (pc4 + (t >> 0) * 0) * 4];
    // (proper prefetch below; the above is replaced in-loop)
#pragma unroll
    for (int t = 0; t < 4; t++) {
        int i = tid + t * 256;            // 0..1023
        int row = i >> 5, c4 = i & 31;
        pf[t] = *(const float4*)&W2[(size_t)row * JTOT + j0 + c4 * 4];
    }

    for (int kp = 0; kp < 8; kp++) {
        __syncthreads();
        // convert prefetched panel -> smem bf16 hi/lo
#pragma unroll
        for (int t = 0; t < 4; t++) {
            int i = tid + t * 256;
            int row = i >> 5, c4 = i & 31;
            u32 h0, l0, h1, l1;
            split2(pf[t].x, pf[t].y, h0, l0);
            split2(pf[t].z, pf[t].w, h1, l1);
            *(uint2*)(dynsm + E_BHI + row * EBB + c4 * 8) = make_uint2(h0, h1);
            *(uint2*)(dynsm + E_BLO + row * EBB + c4 * 8) = make_uint2(l0, l1);
        }
        __syncthreads();
        // issue next panel's global loads (hide under MMA)
        if (kp < 7) {
#pragma unroll
            for (int t = 0; t < 4; t++) {
                int i = tid + t * 256;
                int row = i >> 5, c4 = i & 31;
                pf[t] = *(const float4*)&W2[(size_t)((kp + 1) * 32 + row) * JTOT +
                                            j0 + c4 * 4];
            }
        }

#pragma unroll
        for (int p = 0; p < 3; p++) {
            const u32 aOff = (p < 2) ? E_AHI : E_ALO;
            const u32 bOff = (p == 1) ? E_BLO : E_BHI;
#pragma unroll
            for (int ks = 0; ks < 2; ks++) {
                u32 a0[4], a1[4];
                u32 ka = (u32)((kp * 32 + ks * 16 + kcol) * 2);
                ldsm4(a0, sb + aOff + (R0 + arow) * ESB + ka);
                ldsm4(a1, sb + aOff + (R0 + 16 + arow) * ESB + ka);
                u32 bf[2][4];
                u32 kb = (u32)((ks * 16 + brow) * EBB);
#pragma unroll
                for (int nt = 0; nt < 2; nt++)
                    ldsm4t(bf[nt], sb + bOff + kb + (N0 + nt * 16 + bcol) * 2);
#pragma unroll
                for (int j = 0; j < 4; j++) {
                    u32 b0 = bf[j >> 1][(j & 1) * 2];
                    u32 b1 = bf[j >> 1][(j & 1) * 2 + 1];
                    mma16816(acc[0][j], a0, b0, b1);
                    mma16816(acc[1][j], a1, b0, b1);
                }
            }
        }
    }

    // ---- epilogue ----
#pragma unroll
    for (int mt = 0; mt < 2; mt++) {
        int m = R0 + mt * 16 + (L >> 2);
#pragma unroll
        for (int j = 0; j < 4; j++) {
            int n = j0 + N0 + j * 8 + (L & 3) * 2;
            float b20 = __ldg(&b2[n]), b21 = __ldg(&b2[n + 1]);
            *(float2*)&g_buf0[(size_t)m * JTOT + n] =
                make_float2(acc[mt][j][0] + b20, acc[mt][j][1] + b21);
            *(float2*)&g_buf0[(size_t)(m + 8) * JTOT + n] =
                make_float2(acc[mt][j][2] + b20, acc[mt][j][3] + b21);
        }
    }
}

// ===========================================================================
// K3/K4: fused GCN layer.  M=128 rows (126 out + halo), N=128 in two halves.
// smem 102KB, 2 blocks/SM.  grid(17,64) block(256).
// ===========================================================================
#define GSB       272                      // A/B row stride bytes (136 halfs)
#define G_AHI     0
#define G_ALO     34816
#define G_RB      69632                    // shared region: B-half staging / C
#define G_RLO     (G_RB + 17408)
#define G_SMEM    104448
#define SC_STRIDE 68

__global__ __launch_bounds__(256, 2) void k_gcn_mma(const float* __restrict__ Ah,
                                                    const float* __restrict__ gam,
                                                    const float* __restrict__ bet,
                                                    const float* __restrict__ Wout,
                                                    const float* __restrict__ bout,
                                                    float* __restrict__ proj,
                                                    int layer) {
    __shared__ float sAp[128], sAn[128], sGam[128], sBet[128], sWo[128];
    __shared__ float sProj[128];

    const float* in  = layer ? g_buf1 : g_buf0;
    float*       out = g_buf1;

    const int tid = threadIdx.x;
    const int L   = tid & 31;
    const int w   = tid >> 5;
    const int b   = blockIdx.y;
    const int n0  = blockIdx.x * 126;
    const u32 sb  = smem_u32(dynsm);

    if (tid < 128) {
        sGam[tid] = gam[tid];
        sBet[tid] = bet[tid];
        sWo[tid]  = layer ? Wout[tid] : 0.0f;
        sProj[tid] = 0.0f;
        int gi = n0 - 1 + tid;
        sAp[tid] = (gi >= 1 && gi < NNODES) ? Ah[(size_t)gi * NNODES + gi - 1] : 0.0f;
        sAn[tid] = (gi >= 0 && gi < NNODES - 1) ? Ah[(size_t)gi * NNODES + gi + 1] : 0.0f;
    }
    __syncthreads();

    // ---- LN + bf16 split -> A tiles (warp w: rows 16w..16w+15) ----
#pragma unroll 2
    for (int rr = 0; rr < 16; rr++) {
        int r  = w * 16 + rr;
        int gi = min(NNODES - 1, max(0, n0 - 1 + r));
        float4 v = *(const float4*)&in[((size_t)b * NNODES + gi) * GHD + L * 4];
        float s = v.x + v.y + v.z + v.w;
        float q = v.x * v.x + v.y * v.y + v.z * v.z + v.w * v.w;
#pragma unroll
        for (int o = 16; o; o >>= 1) {
            s += __shfl_xor_sync(0xFFFFFFFFu, s, o);
            q += __shfl_xor_sync(0xFFFFFFFFu, q, o);
        }
        float mu   = s * (1.0f / GHD);
        float rstd = rsqrtf(fmaxf(q * (1.0f / GHD) - mu * mu, 0.0f) + LN_EPS);
        int c = L * 4;
        float f0 = (v.x - mu) * rstd * sGam[c + 0] + sBet[c + 0];
        float f1 = (v.y - mu) * rstd * sGam[c + 1] + sBet[c + 1];
        float f2 = (v.z - mu) * rstd * sGam[c + 2] + sBet[c + 2];
        float f3 = (v.w - mu) * rstd * sGam[c + 3] + sBet[c + 3];
        u32 h0, l0, h1, l1;
        split2(f0, f1, h0, l0);
        split2(f2, f3, h1, l1);
        *(uint2*)(dynsm + G_AHI + r * GSB + L * 8) = make_uint2(h0, h1);
        *(uint2*)(dynsm + G_ALO + r * GSB + L * 8) = make_uint2(l0, l1);
    }

    const int mw = w & 3, nwh = w >> 2;
    const int R0 = mw * 32, N0 = nwh * 32;
    const u32 arow = (u32)(L & 15);
    const u32 kcol = (u32)((L >> 4) << 3);
    float* sC = (float*)(dynsm + G_RB);

    for (int h = 0; h < 2; h++) {
        // ---- stage B half (linear copy from prepped image) ----
        if (h) __syncthreads();            // aggregate of prev half done
        {
            uint4* dh = (uint4*)(dynsm + G_RB);
            uint4* dl = (uint4*)(dynsm + G_RLO);
            const uint4* shp = (const uint4*)(g_BH[layer] + h * 64 * 68);
            const uint4* slp = (const uint4*)(g_BL[layer] + h * 64 * 68);
            for (int i = tid; i < 1088; i += 256) {
                dh[i] = shp[i];
                dl[i] = slp[i];
            }
        }
        __syncthreads();

        // ---- MMA: 128M x 64N, 3 passes ----
        float acc[2][4][4];
#pragma unroll
        for (int mt = 0; mt < 2; mt++)
#pragma unroll
            for (int j = 0; j < 4; j++)
#pragma unroll
                for (int c = 0; c < 4; c++) acc[mt][j][c] = 0.0f;

#pragma unroll
        for (int p = 0; p < 3; p++) {
            const u32 aOff = (p < 2) ? G_AHI : G_ALO;
            const u32 bOff = (p == 1) ? (u32)G_RLO : (u32)G_RB;
#pragma unroll
            for (int ks = 0; ks < 8; ks++) {
                u32 kb = (u32)((ks * 16 + kcol) * 2);
                u32 a0[4], a1[4];
                ldsm4(a0, sb + aOff + (R0 + arow) * GSB + kb);
                ldsm4(a1, sb + aOff + (R0 + 16 + arow) * GSB + kb);
                u32 bf[2][4];
#pragma unroll
                for (int nt = 0; nt < 2; nt++)
                    ldsm4(bf[nt], sb + bOff + (N0 + nt * 16 + arow) * GSB + kb);
#pragma unroll
                for (int j = 0; j < 4; j++) {
                    u32 b0 = bf[j >> 1][(j & 1)];
                    u32 b1 = bf[j >> 1][(j & 1) + 2];
                    mma16816(acc[0][j], a0, b0, b1);
                    mma16816(acc[1][j], a1, b0, b1);
                }
            }
        }
        __syncthreads();                   // B reads done -> reuse region as C

        // ---- C frags -> sC (64 cols of this half) ----
#pragma unroll
        for (int mt = 0; mt < 2; mt++) {
            int m = R0 + mt * 16 + (L >> 2);
#pragma unroll
            for (int j = 0; j < 4; j++) {
                int n = N0 + j * 8 + (L & 3) * 2;
                *(float2*)&sC[m * SC_STRIDE + n] =
                    make_float2(acc[mt][j][0], acc[mt][j][1]);
                *(float2*)&sC[(m + 8) * SC_STRIDE + n] =
                    make_float2(acc[mt][j][2], acc[mt][j][3]);
            }
        }
        __syncthreads();

        // ---- aggregate this half's 64 cols ----
        const int cg = h * 64 + L * 2;     // global col, lane covers 2
        for (int r = 1 + w; r <= 126; r += 8) {
            int gi = n0 + r - 1;
            if (gi >= NNODES) continue;
            float2 iv = *(const float2*)&in[((size_t)b * NNODES + gi) * GHD + cg];
            float2 wp = *(const float2*)&sC[(r - 1) * SC_STRIDE + L * 2];
            float2 wn = *(const float2*)&sC[(r + 1) * SC_STRIDE + L * 2];
            float ap = sAp[r], an = sAn[r];
            float2 o;
            o.x = fmaf(an, wn.x, fmaf(ap, wp.x, iv.x));
            o.y = fmaf(an, wn.y, fmaf(ap, wp.y, iv.y));
            if (!layer) {
                *(float2*)&out[((size_t)b * NNODES + gi) * GHD + cg] = o;
            } else {
                float s = o.x * sWo[cg] + o.y * sWo[cg + 1];
#pragma unroll
                for (int off = 16; off; off >>= 1)
                    s += __shfl_xor_sync(0xFFFFFFFFu, s, off);
                if (L == 0) {
                    if (h == 0) sProj[r] = s;
                    else        proj[b * NNODES + gi] = sProj[r] + s + bout[0];
                }
            }
        }
    }
}

// ===========================================================================
extern "C" void kernel_launch(void* const* d_in, const int* in_sizes, int n_in,
                              void* d_out, int out_size) {
    const float* x    = (const float*)d_in[0];
    const float* Ah   = (const float*)d_in[1];
    const float* W1   = (const float*)d_in[2];
    const float* b1   = (const float*)d_in[3];
    const float* W2   = (const float*)d_in[4];
    const float* b2   = (const float*)d_in[5];
    const float* Wg1  = (const float*)d_in[6];
    const float* Wg2  = (const float*)d_in[7];
    const float* g1   = (const float*)d_in[8];
    const float* bb1  = (const float*)d_in[9];
    const float* g2   = (const float*)d_in[10];
    const float* bb2  = (const float*)d_in[11];
    const float* Wout = (const float*)d_in[12];
    const float* bout = (const float*)d_in[13];
    float* out = (float*)d_out;

    cudaFuncSetAttribute(k_enc2_mma, cudaFuncAttributeMaxDynamicSharedMemorySize,
                         E_SMEM);
    cudaFuncSetAttribute(k_gcn_mma, cudaFuncAttributeMaxDynamicSharedMemorySize,
                         G_SMEM);

    k_prep<<<2, GHD>>>(Wg1, Wg2);
    k_enc1<<<BSZ, ENC_HID>>>(x, W1, b1);
    k_enc2_mma<<<JTOT / 128, 256, E_SMEM>>>(W2, b2);
    dim3 gcn_grid(17, BSZ);
    k_gcn_mma<<<gcn_grid, 256, G_SMEM>>>(Ah, g1, bb1, Wout, bout, out, 0);
    k_gcn_mma<<<gcn_grid, 256, G_SMEM>>>(Ah, g2, bb2, Wout, bout, out, 1);
}